// round 16
// baseline (speedup 1.0000x reference)
#include <cuda_runtime.h>
#include <cuda_bf16.h>
#include <math.h>
#include <stdint.h>

// Problem constants
#define L_SEQ  2048
#define NFEAT  1024
#define NHEAD  16
#define DHEAD  64
#define BATCH  2
#define MTOT   (BATCH * L_SEQ)   // 4096
#define NN     (NFEAT * NFEAT)
#define MTN    (MTOT * NFEAT)

// Q pre-scale: (1/sqrt(1024)) * log2(e)  -> softmax computed in base 2
#define QSCALE 0.045084220027780106f

// ---------------------------------------------------------------------------
// Helpers
// ---------------------------------------------------------------------------
__device__ __forceinline__ uint32_t smem_u32(const void* p) {
    uint32_t a;
    asm("{ .reg .u64 t; cvta.to.shared.u64 t, %1; cvt.u32.u64 %0, t; }" : "=r"(a) : "l"(p));
    return a;
}

#define CP_ASYNC16(dst, src) \
    asm volatile("cp.async.cg.shared.global [%0], [%1], 16;" :: "r"(dst), "l"(src))
#define CP_COMMIT()  asm volatile("cp.async.commit_group;" ::: "memory")
#define CP_WAIT(n)   asm volatile("cp.async.wait_group %0;" :: "n"(n) : "memory")

__device__ __forceinline__ void ldmx4(uint32_t (&r)[4], uint32_t addr) {
    asm volatile("ldmatrix.sync.aligned.m8n8.x4.shared.b16 {%0,%1,%2,%3}, [%4];"
        : "=r"(r[0]), "=r"(r[1]), "=r"(r[2]), "=r"(r[3]) : "r"(addr));
}
__device__ __forceinline__ void ldmx4t(uint32_t (&r)[4], uint32_t addr) {
    asm volatile("ldmatrix.sync.aligned.m8n8.x4.trans.shared.b16 {%0,%1,%2,%3}, [%4];"
        : "=r"(r[0]), "=r"(r[1]), "=r"(r[2]), "=r"(r[3]) : "r"(addr));
}

__device__ __forceinline__ void mma16816(float (&d)[4], const uint32_t (&a)[4],
                                         uint32_t b0, uint32_t b1) {
    asm volatile("mma.sync.aligned.m16n8k16.row.col.f32.bf16.bf16.f32 "
        "{%0,%1,%2,%3}, {%4,%5,%6,%7}, {%8,%9}, {%0,%1,%2,%3};"
        : "+f"(d[0]), "+f"(d[1]), "+f"(d[2]), "+f"(d[3])
        : "r"(a[0]), "r"(a[1]), "r"(a[2]), "r"(a[3]), "r"(b0), "r"(b1));
}

// split (x,y) fp32 pair into packed bf16x2 hi + bf16x2 lo (round-to-nearest)
__device__ __forceinline__ void split2(float x, float y, uint32_t& h, uint32_t& l) {
    __nv_bfloat16 hx = __float2bfloat16(x), hy = __float2bfloat16(y);
    __nv_bfloat162 hh; hh.x = hx; hh.y = hy;
    __nv_bfloat162 ll;
    ll.x = __float2bfloat16(x - __bfloat162float(hx));
    ll.y = __float2bfloat16(y - __bfloat162float(hy));
    h = *reinterpret_cast<uint32_t*>(&hh);
    l = *reinterpret_cast<uint32_t*>(&ll);
}

// FAST truncation split for the attention P matrix: hi = top 16 bits (PRMT),
// lo = x - hi (exact fp32 sub), one cvt per pair. ~half the ops of split2.
__device__ __forceinline__ void split2t(float x, float y, uint32_t& h, uint32_t& l) {
    uint32_t xu = __float_as_uint(x), yu = __float_as_uint(y);
    h = __byte_perm(xu, yu, 0x7632);           // {y_hi16, x_hi16}
    float xl = x - __uint_as_float(xu & 0xFFFF0000u);
    float yl = y - __uint_as_float(yu & 0xFFFF0000u);
    asm("cvt.rn.bf16x2.f32 %0, %1, %2;" : "=r"(l) : "f"(yl), "f"(xl));
}

// ---------------------------------------------------------------------------
// Device scratch
// ---------------------------------------------------------------------------
__device__ __nv_bfloat16 g_Ch  [NN],      g_Cl  [NN];       // cosine matrix
__device__ __nv_bfloat16 g_Xh  [MTN],     g_Xl  [MTN];
__device__ __nv_bfloat16 g_WallH[3 * NN], g_WallL[3 * NN];  // [Wq;Wk;Wv]
__device__ __nv_bfloat16 g_WpH [3 * NN],  g_WpL [3 * NN];   // [Wq;Wk;Wv] @ C
__device__ __nv_bfloat16 g_WoH [NN],      g_WoL [NN];
__device__ __nv_bfloat16 g_QKVH[3 * MTN], g_QKVL[3 * MTN];  // stacked Q|K|V
__device__ __nv_bfloat16 g_AH  [MTN],     g_AL  [MTN];
__device__ float g_bqkv[3 * NFEAT];                          // [bq*QSCALE|bk|bv]

// ---------------------------------------------------------------------------
// Unified prep: gen_cos + split X + split weights + bias concat, one launch.
// ---------------------------------------------------------------------------
#define PREP_BLOCKS (4096 + 16384 + 16384 + 12)
__global__ void prep_kernel(const float* __restrict__ X,
                            const float* __restrict__ Wq, const float* __restrict__ Wk,
                            const float* __restrict__ Wv, const float* __restrict__ Wo,
                            const float* __restrict__ bq, const float* __restrict__ bk,
                            const float* __restrict__ bv) {
    int b = blockIdx.x;
    int tid = threadIdx.x;
    if (b < 4096) {
        int idx = b * 256 + tid;                 // cos matrix
        int k = idx >> 10, n = idx & 1023;
        int kn = (k * n) & 1023;
        float v = cosf((float)kn * 6.135923151542565e-3f) * 9.765625e-4f;
        __nv_bfloat16 h = __float2bfloat16(v);
        g_Ch[idx] = h;
        g_Cl[idx] = __float2bfloat16(v - __bfloat162float(h));
    } else if (b < 20480) {
        int i = (b - 4096) * 256 + tid;          // split X
        float x = X[i];
        __nv_bfloat16 h = __float2bfloat16(x);
        g_Xh[i] = h;
        g_Xl[i] = __float2bfloat16(x - __bfloat162float(h));
    } else if (b < 36864) {
        int idx = (b - 20480) * 256 + tid;       // split weights (4*NN)
        int w = idx >> 20;
        int i = idx & (NN - 1);
        const float* src = (w == 0) ? Wq : (w == 1) ? Wk : (w == 2) ? Wv : Wo;
        float x = src[i];
        __nv_bfloat16 h = __float2bfloat16(x);
        __nv_bfloat16 l = __float2bfloat16(x - __bfloat162float(h));
        if (w < 3) { g_WallH[w * NN + i] = h; g_WallL[w * NN + i] = l; }
        else       { g_WoH[i] = h;            g_WoL[i] = l; }
    } else {
        int i = (b - 36864) * 256 + tid;         // bias concat (bq pre-scaled)
        if (i < 3 * NFEAT) {
            if (i < 1024)      g_bqkv[i] = bq[i] * QSCALE;
            else if (i < 2048) g_bqkv[i] = bk[i & 1023];
            else               g_bqkv[i] = bv[i & 1023];
        }
    }
}

// ---------------------------------------------------------------------------
// Split-bf16 NT GEMM on mma.sync, 8 warps (64x32 warp tile), BK=32,
// 3-stage single-barrier cp.async pipeline (R12 order), 2 CTAs/SM.
//   Out = (A @ B^T) * matScale(mat) + bias; D ~= AhBh + AhBl + AlBh.
// ---------------------------------------------------------------------------
#define STAGE_BYTES 32768                      // sA 16KB + sB 16KB
#define GEMM_STAGES 3
#define GEMM_SMEM   (GEMM_STAGES * STAGE_BYTES + 128)
#define NCHUNK      32                         // K=1024 / 32

__global__ __launch_bounds__(256, 2) void mma_gemm_kernel(
    const __nv_bfloat16* __restrict__ Ah, const __nv_bfloat16* __restrict__ Al,
    const __nv_bfloat16* __restrict__ Bh, const __nv_bfloat16* __restrict__ Bl,
    const float* __restrict__ bias, float* __restrict__ outF,
    __nv_bfloat16* __restrict__ outH, __nv_bfloat16* __restrict__ outL,
    size_t matStride, float qScale)
{
    extern __shared__ char sraw[];
    uint32_t base = smem_u32(sraw);
    base = (base + 127) & ~127u;

    const int tid  = threadIdx.x;
    const int lane = tid & 31;
    const int wid  = tid >> 5;
    const int wm   = wid & 1;                  // 2 warp rows (64 each)
    const int wn   = wid >> 1;                 // 4 warp cols (32 each)
    const int bx = blockIdx.x, by = blockIdx.y;

    const size_t aBase = (size_t)by * 128 * 1024;
    const size_t bBase = (size_t)bx * 128 * 1024;

    float acc[4][4][4];
    #pragma unroll
    for (int i = 0; i < 4; i++)
        #pragma unroll
        for (int j = 0; j < 4; j++)
            #pragma unroll
            for (int r = 0; r < 4; r++) acc[i][j][r] = 0.f;

    #define ISSUE_STAGE(c) do { \
        const uint32_t sb = base + ((c) % GEMM_STAGES) * STAGE_BYTES; \
        const int k0 = (c) * 32; \
        _Pragma("unroll") \
        for (int s = 0; s < 8; s++) { \
            int i  = tid + s * 256; \
            int tl = i >> 10; \
            int j  = i & 1023; \
            int row = j >> 3; \
            int ch  = j & 7; \
            uint32_t dst = sb + (uint32_t)tl * 16384u + (uint32_t)row * 128u \
                         + (uint32_t)((ch ^ (row & 7)) * 16); \
            size_t off = (size_t)row * 1024 + k0 + (ch & 3) * 8; \
            const __nv_bfloat16* src = (tl == 0) \
                ? ((ch < 4 ? Ah : Al) + aBase + off) \
                : ((ch < 4 ? Bh : Bl) + bBase + off); \
            CP_ASYNC16(dst, src); \
        } \
        CP_COMMIT(); \
    } while (0)

    ISSUE_STAGE(0);
    ISSUE_STAGE(1);

    #pragma unroll 1
    for (int c = 0; c < NCHUNK; c++) {
        if (c < NCHUNK - 1) { CP_WAIT(1); } else { CP_WAIT(0); }
        __syncthreads();
        if (c + 2 < NCHUNK) ISSUE_STAGE(c + 2);

        const uint32_t sA = base + (c % GEMM_STAGES) * STAGE_BYTES;
        const uint32_t sB = sA + 16384;

        #pragma unroll
        for (int ks = 0; ks < 2; ks++) {
            uint32_t ahf[4][4];
            #pragma unroll
            for (int mi = 0; mi < 4; mi++) {
                int row = wm * 64 + mi * 16 + (lane & 15);
                int chH = ks * 2 + (lane >> 4);
                ldmx4(ahf[mi], sA + row * 128 + ((chH ^ (row & 7)) * 16));
            }
            uint32_t bhf[4][2], blf[4][2];
            #pragma unroll
            for (int p = 0; p < 2; p++) {
                int row = wn * 32 + p * 16 + (lane >> 4) * 8 + (lane & 7);
                int chH = ks * 2 + ((lane >> 3) & 1);
                int chL = chH + 4;
                uint32_t th[4], tl4[4];
                ldmx4(th,  sB + row * 128 + ((chH ^ (row & 7)) * 16));
                ldmx4(tl4, sB + row * 128 + ((chL ^ (row & 7)) * 16));
                bhf[2*p][0] = th[0];   bhf[2*p][1] = th[1];
                bhf[2*p+1][0] = th[2]; bhf[2*p+1][1] = th[3];
                blf[2*p][0] = tl4[0];  blf[2*p][1] = tl4[1];
                blf[2*p+1][0] = tl4[2]; blf[2*p+1][1] = tl4[3];
            }
            #pragma unroll
            for (int mi = 0; mi < 4; mi++)
                #pragma unroll
                for (int nj = 0; nj < 4; nj++) {
                    mma16816(acc[mi][nj], ahf[mi], bhf[nj][0], bhf[nj][1]);
                    mma16816(acc[mi][nj], ahf[mi], blf[nj][0], blf[nj][1]);
                }
            uint32_t alf[4][4];
            #pragma unroll
            for (int mi = 0; mi < 4; mi++) {
                int row = wm * 64 + mi * 16 + (lane & 15);
                int chL = ks * 2 + (lane >> 4) + 4;
                ldmx4(alf[mi], sA + row * 128 + ((chL ^ (row & 7)) * 16));
            }
            #pragma unroll
            for (int mi = 0; mi < 4; mi++)
                #pragma unroll
                for (int nj = 0; nj < 4; nj++)
                    mma16816(acc[mi][nj], alf[mi], bhf[nj][0], bhf[nj][1]);
        }
    }

    // epilogue: route by mat = bx >> 3 into stacked outputs
    const int mat = bx >> 3;
    const float scl = (mat == 0) ? qScale : 1.0f;
    const size_t matOff = (size_t)mat * matStride;
    const int r0 = by * 128 + wm * 64 + (lane >> 2);
    const int cloc0 = (bx & 7) * 128 + wn * 32 + (lane & 3) * 2;
    const int cb0 = bx * 128 + wn * 32 + (lane & 3) * 2;
    #pragma unroll
    for (int mi = 0; mi < 4; mi++)
        #pragma unroll
        for (int nj = 0; nj < 4; nj++)
            #pragma unroll
            for (int h = 0; h < 2; h++) {
                int r = r0 + mi * 16 + h * 8;
                float v0 = acc[mi][nj][2*h+0] * scl;
                float v1 = acc[mi][nj][2*h+1] * scl;
                if (bias) {
                    v0 += bias[cb0 + nj * 8];
                    v1 += bias[cb0 + nj * 8 + 1];
                }
                size_t o = matOff + (size_t)r * 1024 + cloc0 + nj * 8;
                if (outF) *(float2*)(outF + o) = make_float2(v0, v1);
                if (outH) {
                    uint32_t ph, pl;
                    split2(v0, v1, ph, pl);
                    *(uint32_t*)(outH + o) = ph;
                    *(uint32_t*)(outL + o) = pl;
                }
            }
}

// ---------------------------------------------------------------------------
// Attention step body, templated on DIAG. Base-2 softmax (Q pre-scaled).
// P split uses the fast truncation split (split2t).
// ---------------------------------------------------------------------------
template<bool DIAG>
__device__ __forceinline__ void attn_step(
    uint32_t kb, int lane, int qrow0, int kc_base,
    const uint32_t (&qh)[4][4], const uint32_t (&ql)[4][4],
    float& m0, float& m1, float& l0, float& l1, float (&o)[8][4])
{
    float s[8][4];
    #pragma unroll
    for (int nj = 0; nj < 8; nj++)
        #pragma unroll
        for (int e = 0; e < 4; e++) s[nj][e] = 0.f;

    #pragma unroll
    for (int ks = 0; ks < 4; ks++) {
        #pragma unroll
        for (int p = 0; p < 4; p++) {
            int row = p * 16 + (lane >> 4) * 8 + (lane & 7);
            int ch = ks * 2 + ((lane >> 3) & 1);
            uint32_t sw = (uint32_t)((ch ^ (row & 7)) * 16);
            uint32_t th[4], tl4[4];
            ldmx4(th,  kb + row * 128u + sw);
            ldmx4(tl4, kb + 8192u + row * 128u + sw);
            mma16816(s[2*p],   qh[ks], th[0],  th[1]);
            mma16816(s[2*p],   qh[ks], tl4[0], tl4[1]);
            mma16816(s[2*p],   ql[ks], th[0],  th[1]);
            mma16816(s[2*p+1], qh[ks], th[2],  th[3]);
            mma16816(s[2*p+1], qh[ks], tl4[2], tl4[3]);
            mma16816(s[2*p+1], ql[ks], th[2],  th[3]);
        }
    }

    float mx0 = -INFINITY, mx1 = -INFINITY;
    #pragma unroll
    for (int nj = 0; nj < 8; nj++) {
        if (DIAG) {
            int kc = kc_base + nj * 8 + (lane & 3) * 2;
            if (kc     > qrow0)     s[nj][0] = -INFINITY;
            if (kc + 1 > qrow0)     s[nj][1] = -INFINITY;
            if (kc     > qrow0 + 8) s[nj][2] = -INFINITY;
            if (kc + 1 > qrow0 + 8) s[nj][3] = -INFINITY;
        }
        mx0 = fmaxf(mx0, fmaxf(s[nj][0], s[nj][1]));
        mx1 = fmaxf(mx1, fmaxf(s[nj][2], s[nj][3]));
    }
    mx0 = fmaxf(mx0, __shfl_xor_sync(0xffffffffu, mx0, 1));
    mx0 = fmaxf(mx0, __shfl_xor_sync(0xffffffffu, mx0, 2));
    mx1 = fmaxf(mx1, __shfl_xor_sync(0xffffffffu, mx1, 1));
    mx1 = fmaxf(mx1, __shfl_xor_sync(0xffffffffu, mx1, 2));

    float nm0 = fmaxf(m0, mx0), nm1 = fmaxf(m1, mx1);
    float a0 = exp2f(m0 - nm0), a1 = exp2f(m1 - nm1);
    float rs0 = 0.f, rs1 = 0.f;
    #pragma unroll
    for (int nj = 0; nj < 8; nj++) {
        s[nj][0] = exp2f(s[nj][0] - nm0);
        s[nj][1] = exp2f(s[nj][1] - nm0);
        s[nj][2] = exp2f(s[nj][2] - nm1);
        s[nj][3] = exp2f(s[nj][3] - nm1);
        rs0 += s[nj][0] + s[nj][1];
        rs1 += s[nj][2] + s[nj][3];
    }
    rs0 += __shfl_xor_sync(0xffffffffu, rs0, 1);
    rs0 += __shfl_xor_sync(0xffffffffu, rs0, 2);
    rs1 += __shfl_xor_sync(0xffffffffu, rs1, 1);
    rs1 += __shfl_xor_sync(0xffffffffu, rs1, 2);
    l0 = l0 * a0 + rs0; l1 = l1 * a1 + rs1;
    m0 = nm0; m1 = nm1;
    #pragma unroll
    for (int dj = 0; dj < 8; dj++) {
        o[dj][0] *= a0; o[dj][1] *= a0;
        o[dj][2] *= a1; o[dj][3] *= a1;
    }

    #pragma unroll
    for (int kf = 0; kf < 4; kf++) {
        uint32_t ph[4], pl[4];
        split2t(s[2*kf][0],   s[2*kf][1],   ph[0], pl[0]);
        split2t(s[2*kf][2],   s[2*kf][3],   ph[1], pl[1]);
        split2t(s[2*kf+1][0], s[2*kf+1][1], ph[2], pl[2]);
        split2t(s[2*kf+1][2], s[2*kf+1][3], ph[3], pl[3]);
        #pragma unroll
        for (int dp = 0; dp < 4; dp++) {
            int row = kf * 16 + ((lane >> 3) & 1) * 8 + (lane & 7);
            int ch = dp * 2 + (lane >> 4);
            uint32_t sw = (uint32_t)((ch ^ (row & 7)) * 16);
            uint32_t vh4[4], vl4[4];
            ldmx4t(vh4, kb + 16384u + row * 128u + sw);
            ldmx4t(vl4, kb + 24576u + row * 128u + sw);
            mma16816(o[2*dp],   ph, vh4[0], vh4[1]);
            mma16816(o[2*dp],   ph, vl4[0], vl4[1]);
            mma16816(o[2*dp],   pl, vh4[0], vh4[1]);
            mma16816(o[2*dp+1], ph, vh4[2], vh4[3]);
            mma16816(o[2*dp+1], ph, vl4[2], vl4[3]);
            mma16816(o[2*dp+1], pl, vh4[2], vh4[3]);
        }
    }
}

// ---------------------------------------------------------------------------
// Tensor-core causal flash attention, split-bf16 (3-term) QK^T and PV.
// Q fragments loaded DIRECTLY from gmem; 3-stage KV ring (depth-2 prefetch);
// diagonal tile peeled. Grid: x = bh (32), y: qt = 31 - blockIdx.y.
// ---------------------------------------------------------------------------
#define ATTN_SMEM (3 * 32768 + 128)

__global__ __launch_bounds__(128, 2) void attn_mma_kernel(
    const __nv_bfloat16* __restrict__ Qh_g, const __nv_bfloat16* __restrict__ Ql_g,
    const __nv_bfloat16* __restrict__ Kh_g, const __nv_bfloat16* __restrict__ Kl_g,
    const __nv_bfloat16* __restrict__ Vh_g, const __nv_bfloat16* __restrict__ Vl_g,
    __nv_bfloat16* __restrict__ Oh, __nv_bfloat16* __restrict__ Ol)
{
    extern __shared__ char sraw[];
    uint32_t base = smem_u32(sraw);
    base = (base + 127) & ~127u;

    const int tid  = threadIdx.x;
    const int lane = tid & 31;
    const int wm   = tid >> 5;
    const int qt   = 31 - blockIdx.y;          // longest-first scheduling
    const int q0   = qt * 64;
    const int bh   = blockIdx.x;
    const size_t rowBase = (size_t)(bh >> 4) * L_SEQ;
    const int colBase = (bh & 15) * DHEAD;
    const int T = qt + 1;

    #define KVBASE(buf) (base + (uint32_t)(buf) * 32768u)

    #define ISSUE_KV(jt, buf) do { \
        const __nv_bfloat16* b0_ = Kh_g + (rowBase + (jt) * 64) * NFEAT + colBase; \
        const __nv_bfloat16* b1_ = Kl_g + (rowBase + (jt) * 64) * NFEAT + colBase; \
        const __nv_bfloat16* b2_ = Vh_g + (rowBase + (jt) * 64) * NFEAT + colBase; \
        const __nv_bfloat16* b3_ = Vl_g + (rowBase + (jt) * 64) * NFEAT + colBase; \
        _Pragma("unroll") \
        for (int s = 0; s < 16; s++) { \
            int i = tid + s * 128; \
            int tl = i >> 9, j = i & 511, row = j >> 3, ch = j & 7; \
            uint32_t dst = KVBASE(buf) + (uint32_t)tl * 8192u + row * 128u \
                         + ((ch ^ (row & 7)) * 16); \
            size_t off = (size_t)row * NFEAT + ch * 8; \
            const __nv_bfloat16* src = (tl == 0 ? b0_ : tl == 1 ? b1_ : \
                                        tl == 2 ? b2_ : b3_) + off; \
            CP_ASYNC16(dst, src); \
        } \
        CP_COMMIT(); \
    } while (0)

    // Q fragments straight from gmem (mma A-layout, 4B loads, pre-scaled)
    uint32_t qh[4][4], ql[4][4];
    {
        const size_t r0o = (rowBase + q0 + wm * 16 + (lane >> 2)) * NFEAT
                         + colBase + (lane & 3) * 2;
        #pragma unroll
        for (int ks = 0; ks < 4; ks++) {
            size_t k0 = r0o + ks * 16;
            qh[ks][0] = *(const uint32_t*)(Qh_g + k0);
            qh[ks][1] = *(const uint32_t*)(Qh_g + k0 + 8 * NFEAT);
            qh[ks][2] = *(const uint32_t*)(Qh_g + k0 + 8);
            qh[ks][3] = *(const uint32_t*)(Qh_g + k0 + 8 * NFEAT + 8);
            ql[ks][0] = *(const uint32_t*)(Ql_g + k0);
            ql[ks][1] = *(const uint32_t*)(Ql_g + k0 + 8 * NFEAT);
            ql[ks][2] = *(const uint32_t*)(Ql_g + k0 + 8);
            ql[ks][3] = *(const uint32_t*)(Ql_g + k0 + 8 * NFEAT + 8);
        }
    }

    ISSUE_KV(0, 0);
    if (T > 1) ISSUE_KV(1, 1);

    float m0 = -INFINITY, m1 = -INFINITY, l0 = 0.f, l1 = 0.f;
    float o[8][4];
    #pragma unroll
    for (int dj = 0; dj < 8; dj++)
        #pragma unroll
        for (int e = 0; e < 4; e++) o[dj][e] = 0.f;

    const int qrow0 = q0 + wm * 16 + (lane >> 2);

    // mainloop: t = 0 .. T-2 (no diagonal masking), 3-stage ring
    #pragma unroll 1
    for (int t = 0; t < T - 1; t++) {
        CP_WAIT(1);                            // stage t resident
        __syncthreads();                       // visible; (t+2)%3 readers done
        if (t + 2 < T) ISSUE_KV(t + 2, (t + 2) % 3);
        attn_step<false>(KVBASE(t % 3), lane, qrow0, t * 64,
                         qh, ql, m0, m1, l0, l1, o);
    }

    // final (diagonal) tile: t = T-1 = qt
    {
        const int t = T - 1;
        CP_WAIT(0);
        __syncthreads();
        attn_step<true>(KVBASE(t % 3), lane, qrow0, t * 64,
                        qh, ql, m0, m1, l0, l1, o);
    }

    const float i0 = 1.f / l0, i1 = 1.f / l1;
    const int qrow = q0 + wm * 16 + (lane >> 2);
    #pragma unroll
    for (int dj = 0; dj < 8; dj++) {
        int col = colBase + dj * 8 + (lane & 3) * 2;
        size_t off0 = (rowBase + qrow) * NFEAT + col;
        size_t off1 = (rowBase + qrow + 8) * NFEAT + col;
        uint32_t h, l;
        split2(o[dj][0] * i0, o[dj][1] * i0, h, l);
        *(uint32_t*)(Oh + off0) = h; *(uint32_t*)(Ol + off0) = l;
        split2(o[dj][2] * i1, o[dj][3] * i1, h, l);
        *(uint32_t*)(Oh + off1) = h; *(uint32_t*)(Ol + off1) = l;
    }
}

// ---------------------------------------------------------------------------
// Launch
// ---------------------------------------------------------------------------
extern "C" void kernel_launch(void* const* d_in, const int* in_sizes, int n_in,
                              void* d_out, int out_size)
{
    const float* X  = (const float*)d_in[0];
    const float* Wq = (const float*)d_in[1];
    const float* bq = (const float*)d_in[2];
    const float* Wk = (const float*)d_in[3];
    const float* bk = (const float*)d_in[4];
    const float* Wv = (const float*)d_in[5];
    const float* bv = (const float*)d_in[6];
    const float* Wo = (const float*)d_in[7];
    const float* bo = (const float*)d_in[8];
    float* out = (float*)d_out;

    __nv_bfloat16 *Ch, *Cl, *Xh, *Xl, *WallH, *WallL, *WpH, *WpL, *WoH, *WoL;
    __nv_bfloat16 *QKVH, *QKVL, *AH, *AL;
    float* bqkv;
    cudaGetSymbolAddress((void**)&Ch,    g_Ch);    cudaGetSymbolAddress((void**)&Cl,    g_Cl);
    cudaGetSymbolAddress((void**)&Xh,    g_Xh);    cudaGetSymbolAddress((void**)&Xl,    g_Xl);
    cudaGetSymbolAddress((void**)&WallH, g_WallH); cudaGetSymbolAddress((void**)&WallL, g_WallL);
    cudaGetSymbolAddress((void**)&WpH,   g_WpH);   cudaGetSymbolAddress((void**)&WpL,   g_WpL);
    cudaGetSymbolAddress((void**)&WoH,   g_WoH);   cudaGetSymbolAddress((void**)&WoL,   g_WoL);
    cudaGetSymbolAddress((void**)&QKVH,  g_QKVH);  cudaGetSymbolAddress((void**)&QKVL,  g_QKVL);
    cudaGetSymbolAddress((void**)&AH,    g_AH);    cudaGetSymbolAddress((void**)&AL,    g_AL);
    cudaGetSymbolAddress((void**)&bqkv,  g_bqkv);

    cudaFuncSetAttribute(mma_gemm_kernel,
                         cudaFuncAttributeMaxDynamicSharedMemorySize, GEMM_SMEM);
    cudaFuncSetAttribute(attn_mma_kernel,
                         cudaFuncAttributeMaxDynamicSharedMemorySize, ATTN_SMEM);

    // 1) unified prep (cos + splits + bias concat w/ QSCALE-scaled bq)
    prep_kernel<<<PREP_BLOCKS, 256>>>(X, Wq, Wk, Wv, Wo, bq, bk, bv);

    // 2) fold IFFT: W' = [Wq;Wk;Wv] @ C   (M=3072 -> grid (8,24))
    mma_gemm_kernel<<<dim3(8, 24), 256, GEMM_SMEM>>>(
        WallH, WallL, Ch, Cl, nullptr, nullptr, WpH, WpL, 0, 1.0f);

    // 3) fused QKV: [Q|K|V] = X @ W'^T (Q scaled by QSCALE) + bqkv
    mma_gemm_kernel<<<dim3(24, 32), 256, GEMM_SMEM>>>(
        Xh, Xl, WpH, WpL, bqkv, nullptr, QKVH, QKVL, (size_t)MTN, QSCALE);

    // 4) tensor-core causal attention (q-tile 64, longest blocks first)
    attn_mma_kernel<<<dim3(BATCH * NHEAD, L_SEQ / 64), 128, ATTN_SMEM>>>(
        QKVH, QKVL, QKVH + MTN, QKVL + MTN, QKVH + 2 * (size_t)MTN, QKVL + 2 * (size_t)MTN,
        AH, AL);

    // 5) out = A @ Wo^T + bo
    mma_gemm_kernel<<<dim3(8, 32), 256, GEMM_SMEM>>>(
        AH, AL, WoH, WoL, bo, out, nullptr, nullptr, 0, 1.0f);
}

// round 17
// speedup vs baseline: 1.0064x; 1.0064x over previous
#include <cuda_runtime.h>
#include <cuda_bf16.h>
#include <math.h>
#include <stdint.h>

// Problem constants
#define L_SEQ  2048
#define NFEAT  1024
#define NHEAD  16
#define DHEAD  64
#define BATCH  2
#define MTOT   (BATCH * L_SEQ)   // 4096
#define NN     (NFEAT * NFEAT)
#define MTN    (MTOT * NFEAT)

// Q pre-scale: (1/sqrt(1024)) * log2(e)  -> softmax computed in base 2
#define QSCALE 0.045084220027780106f

// ---------------------------------------------------------------------------
// Helpers
// ---------------------------------------------------------------------------
__device__ __forceinline__ uint32_t smem_u32(const void* p) {
    uint32_t a;
    asm("{ .reg .u64 t; cvta.to.shared.u64 t, %1; cvt.u32.u64 %0, t; }" : "=r"(a) : "l"(p));
    return a;
}

#define CP_ASYNC16(dst, src) \
    asm volatile("cp.async.cg.shared.global [%0], [%1], 16;" :: "r"(dst), "l"(src))
#define CP_COMMIT()  asm volatile("cp.async.commit_group;" ::: "memory")
#define CP_WAIT(n)   asm volatile("cp.async.wait_group %0;" :: "n"(n) : "memory")

__device__ __forceinline__ void ldmx4(uint32_t (&r)[4], uint32_t addr) {
    asm volatile("ldmatrix.sync.aligned.m8n8.x4.shared.b16 {%0,%1,%2,%3}, [%4];"
        : "=r"(r[0]), "=r"(r[1]), "=r"(r[2]), "=r"(r[3]) : "r"(addr));
}
__device__ __forceinline__ void ldmx4t(uint32_t (&r)[4], uint32_t addr) {
    asm volatile("ldmatrix.sync.aligned.m8n8.x4.trans.shared.b16 {%0,%1,%2,%3}, [%4];"
        : "=r"(r[0]), "=r"(r[1]), "=r"(r[2]), "=r"(r[3]) : "r"(addr));
}

__device__ __forceinline__ void mma16816(float (&d)[4], const uint32_t (&a)[4],
                                         uint32_t b0, uint32_t b1) {
    asm volatile("mma.sync.aligned.m16n8k16.row.col.f32.bf16.bf16.f32 "
        "{%0,%1,%2,%3}, {%4,%5,%6,%7}, {%8,%9}, {%0,%1,%2,%3};"
        : "+f"(d[0]), "+f"(d[1]), "+f"(d[2]), "+f"(d[3])
        : "r"(a[0]), "r"(a[1]), "r"(a[2]), "r"(a[3]), "r"(b0), "r"(b1));
}

// split (x,y) fp32 pair into packed bf16x2 hi + bf16x2 lo residual
__device__ __forceinline__ void split2(float x, float y, uint32_t& h, uint32_t& l) {
    __nv_bfloat16 hx = __float2bfloat16(x), hy = __float2bfloat16(y);
    __nv_bfloat162 hh; hh.x = hx; hh.y = hy;
    __nv_bfloat162 ll;
    ll.x = __float2bfloat16(x - __bfloat162float(hx));
    ll.y = __float2bfloat16(y - __bfloat162float(hy));
    h = *reinterpret_cast<uint32_t*>(&hh);
    l = *reinterpret_cast<uint32_t*>(&ll);
}

// ---------------------------------------------------------------------------
// Device scratch
// ---------------------------------------------------------------------------
__device__ __nv_bfloat16 g_Ch  [NN],      g_Cl  [NN];       // cosine matrix
__device__ __nv_bfloat16 g_Xh  [MTN],     g_Xl  [MTN];
__device__ __nv_bfloat16 g_WallH[3 * NN], g_WallL[3 * NN];  // [Wq;Wk;Wv]
__device__ __nv_bfloat16 g_WpH [3 * NN],  g_WpL [3 * NN];   // [Wq;Wk;Wv] @ C
__device__ __nv_bfloat16 g_WoH [NN],      g_WoL [NN];
__device__ __nv_bfloat16 g_QKVH[3 * MTN], g_QKVL[3 * MTN];  // stacked Q|K|V
__device__ __nv_bfloat16 g_AH  [MTN],     g_AL  [MTN];
__device__ float g_bqkv[3 * NFEAT];                          // [bq*QSCALE|bk|bv]

// ---------------------------------------------------------------------------
// Unified prep: gen_cos + split X + split weights + bias concat, one launch.
// ---------------------------------------------------------------------------
#define PREP_BLOCKS (4096 + 16384 + 16384 + 12)
__global__ void prep_kernel(const float* __restrict__ X,
                            const float* __restrict__ Wq, const float* __restrict__ Wk,
                            const float* __restrict__ Wv, const float* __restrict__ Wo,
                            const float* __restrict__ bq, const float* __restrict__ bk,
                            const float* __restrict__ bv) {
    int b = blockIdx.x;
    int tid = threadIdx.x;
    if (b < 4096) {
        int idx = b * 256 + tid;                 // cos matrix
        int k = idx >> 10, n = idx & 1023;
        int kn = (k * n) & 1023;
        float v = cosf((float)kn * 6.135923151542565e-3f) * 9.765625e-4f;
        __nv_bfloat16 h = __float2bfloat16(v);
        g_Ch[idx] = h;
        g_Cl[idx] = __float2bfloat16(v - __bfloat162float(h));
    } else if (b < 20480) {
        int i = (b - 4096) * 256 + tid;          // split X
        float x = X[i];
        __nv_bfloat16 h = __float2bfloat16(x);
        g_Xh[i] = h;
        g_Xl[i] = __float2bfloat16(x - __bfloat162float(h));
    } else if (b < 36864) {
        int idx = (b - 20480) * 256 + tid;       // split weights (4*NN)
        int w = idx >> 20;
        int i = idx & (NN - 1);
        const float* src = (w == 0) ? Wq : (w == 1) ? Wk : (w == 2) ? Wv : Wo;
        float x = src[i];
        __nv_bfloat16 h = __float2bfloat16(x);
        __nv_bfloat16 l = __float2bfloat16(x - __bfloat162float(h));
        if (w < 3) { g_WallH[w * NN + i] = h; g_WallL[w * NN + i] = l; }
        else       { g_WoH[i] = h;            g_WoL[i] = l; }
    } else {
        int i = (b - 36864) * 256 + tid;         // bias concat (bq pre-scaled)
        if (i < 3 * NFEAT) {
            if (i < 1024)      g_bqkv[i] = bq[i] * QSCALE;
            else if (i < 2048) g_bqkv[i] = bk[i & 1023];
            else               g_bqkv[i] = bv[i & 1023];
        }
    }
}

// ---------------------------------------------------------------------------
// Split-bf16 NT GEMM on mma.sync, 8 warps (64x32 warp tile), BK=32,
// 3-stage single-barrier cp.async pipeline (R12 order), 2 CTAs/SM.
//   Out = (A @ B^T) * matScale(mat) + bias; D ~= AhBh + AhBl + AlBh.
// ---------------------------------------------------------------------------
#define STAGE_BYTES 32768                      // sA 16KB + sB 16KB
#define GEMM_STAGES 3
#define GEMM_SMEM   (GEMM_STAGES * STAGE_BYTES + 128)
#define NCHUNK      32                         // K=1024 / 32

__global__ __launch_bounds__(256, 2) void mma_gemm_kernel(
    const __nv_bfloat16* __restrict__ Ah, const __nv_bfloat16* __restrict__ Al,
    const __nv_bfloat16* __restrict__ Bh, const __nv_bfloat16* __restrict__ Bl,
    const float* __restrict__ bias, float* __restrict__ outF,
    __nv_bfloat16* __restrict__ outH, __nv_bfloat16* __restrict__ outL,
    size_t matStride, float qScale)
{
    extern __shared__ char sraw[];
    uint32_t base = smem_u32(sraw);
    base = (base + 127) & ~127u;

    const int tid  = threadIdx.x;
    const int lane = tid & 31;
    const int wid  = tid >> 5;
    const int wm   = wid & 1;                  // 2 warp rows (64 each)
    const int wn   = wid >> 1;                 // 4 warp cols (32 each)
    const int bx = blockIdx.x, by = blockIdx.y;

    const size_t aBase = (size_t)by * 128 * 1024;
    const size_t bBase = (size_t)bx * 128 * 1024;

    float acc[4][4][4];
    #pragma unroll
    for (int i = 0; i < 4; i++)
        #pragma unroll
        for (int j = 0; j < 4; j++)
            #pragma unroll
            for (int r = 0; r < 4; r++) acc[i][j][r] = 0.f;

    #define ISSUE_STAGE(c) do { \
        const uint32_t sb = base + ((c) % GEMM_STAGES) * STAGE_BYTES; \
        const int k0 = (c) * 32; \
        _Pragma("unroll") \
        for (int s = 0; s < 8; s++) { \
            int i  = tid + s * 256; \
            int tl = i >> 10; \
            int j  = i & 1023; \
            int row = j >> 3; \
            int ch  = j & 7; \
            uint32_t dst = sb + (uint32_t)tl * 16384u + (uint32_t)row * 128u \
                         + (uint32_t)((ch ^ (row & 7)) * 16); \
            size_t off = (size_t)row * 1024 + k0 + (ch & 3) * 8; \
            const __nv_bfloat16* src = (tl == 0) \
                ? ((ch < 4 ? Ah : Al) + aBase + off) \
                : ((ch < 4 ? Bh : Bl) + bBase + off); \
            CP_ASYNC16(dst, src); \
        } \
        CP_COMMIT(); \
    } while (0)

    ISSUE_STAGE(0);
    ISSUE_STAGE(1);

    #pragma unroll 1
    for (int c = 0; c < NCHUNK; c++) {
        if (c < NCHUNK - 1) { CP_WAIT(1); } else { CP_WAIT(0); }
        __syncthreads();
        if (c + 2 < NCHUNK) ISSUE_STAGE(c + 2);

        const uint32_t sA = base + (c % GEMM_STAGES) * STAGE_BYTES;
        const uint32_t sB = sA + 16384;

        #pragma unroll
        for (int ks = 0; ks < 2; ks++) {
            uint32_t ahf[4][4];
            #pragma unroll
            for (int mi = 0; mi < 4; mi++) {
                int row = wm * 64 + mi * 16 + (lane & 15);
                int chH = ks * 2 + (lane >> 4);
                ldmx4(ahf[mi], sA + row * 128 + ((chH ^ (row & 7)) * 16));
            }
            uint32_t bhf[4][2], blf[4][2];
            #pragma unroll
            for (int p = 0; p < 2; p++) {
                int row = wn * 32 + p * 16 + (lane >> 4) * 8 + (lane & 7);
                int chH = ks * 2 + ((lane >> 3) & 1);
                int chL = chH + 4;
                uint32_t th[4], tl4[4];
                ldmx4(th,  sB + row * 128 + ((chH ^ (row & 7)) * 16));
                ldmx4(tl4, sB + row * 128 + ((chL ^ (row & 7)) * 16));
                bhf[2*p][0] = th[0];   bhf[2*p][1] = th[1];
                bhf[2*p+1][0] = th[2]; bhf[2*p+1][1] = th[3];
                blf[2*p][0] = tl4[0];  blf[2*p][1] = tl4[1];
                blf[2*p+1][0] = tl4[2]; blf[2*p+1][1] = tl4[3];
            }
            #pragma unroll
            for (int mi = 0; mi < 4; mi++)
                #pragma unroll
                for (int nj = 0; nj < 4; nj++) {
                    mma16816(acc[mi][nj], ahf[mi], bhf[nj][0], bhf[nj][1]);
                    mma16816(acc[mi][nj], ahf[mi], blf[nj][0], blf[nj][1]);
                }
            uint32_t alf[4][4];
            #pragma unroll
            for (int mi = 0; mi < 4; mi++) {
                int row = wm * 64 + mi * 16 + (lane & 15);
                int chL = ks * 2 + (lane >> 4) + 4;
                ldmx4(alf[mi], sA + row * 128 + ((chL ^ (row & 7)) * 16));
            }
            #pragma unroll
            for (int mi = 0; mi < 4; mi++)
                #pragma unroll
                for (int nj = 0; nj < 4; nj++)
                    mma16816(acc[mi][nj], alf[mi], bhf[nj][0], bhf[nj][1]);
        }
    }

    // epilogue: route by mat = bx >> 3 into stacked outputs
    const int mat = bx >> 3;
    const float scl = (mat == 0) ? qScale : 1.0f;
    const size_t matOff = (size_t)mat * matStride;
    const int r0 = by * 128 + wm * 64 + (lane >> 2);
    const int cloc0 = (bx & 7) * 128 + wn * 32 + (lane & 3) * 2;
    const int cb0 = bx * 128 + wn * 32 + (lane & 3) * 2;
    #pragma unroll
    for (int mi = 0; mi < 4; mi++)
        #pragma unroll
        for (int nj = 0; nj < 4; nj++)
            #pragma unroll
            for (int h = 0; h < 2; h++) {
                int r = r0 + mi * 16 + h * 8;
                float v0 = acc[mi][nj][2*h+0] * scl;
                float v1 = acc[mi][nj][2*h+1] * scl;
                if (bias) {
                    v0 += bias[cb0 + nj * 8];
                    v1 += bias[cb0 + nj * 8 + 1];
                }
                size_t o = matOff + (size_t)r * 1024 + cloc0 + nj * 8;
                if (outF) *(float2*)(outF + o) = make_float2(v0, v1);
                if (outH) {
                    uint32_t ph, pl;
                    split2(v0, v1, ph, pl);
                    *(uint32_t*)(outH + o) = ph;
                    *(uint32_t*)(outL + o) = pl;
                }
            }
}

// ---------------------------------------------------------------------------
// Attention step body, templated on DIAG. Base-2 softmax (Q pre-scaled).
// ---------------------------------------------------------------------------
template<bool DIAG>
__device__ __forceinline__ void attn_step(
    uint32_t kb, int lane, int qrow0, int kc_base,
    const uint32_t (&qh)[4][4], const uint32_t (&ql)[4][4],
    float& m0, float& m1, float& l0, float& l1, float (&o)[8][4])
{
    float s[8][4];
    #pragma unroll
    for (int nj = 0; nj < 8; nj++)
        #pragma unroll
        for (int e = 0; e < 4; e++) s[nj][e] = 0.f;

    #pragma unroll
    for (int ks = 0; ks < 4; ks++) {
        #pragma unroll
        for (int p = 0; p < 4; p++) {
            int row = p * 16 + (lane >> 4) * 8 + (lane & 7);
            int ch = ks * 2 + ((lane >> 3) & 1);
            uint32_t sw = (uint32_t)((ch ^ (row & 7)) * 16);
            uint32_t th[4], tl4[4];
            ldmx4(th,  kb + row * 128u + sw);
            ldmx4(tl4, kb + 8192u + row * 128u + sw);
            mma16816(s[2*p],   qh[ks], th[0],  th[1]);
            mma16816(s[2*p],   qh[ks], tl4[0], tl4[1]);
            mma16816(s[2*p],   ql[ks], th[0],  th[1]);
            mma16816(s[2*p+1], qh[ks], th[2],  th[3]);
            mma16816(s[2*p+1], qh[ks], tl4[2], tl4[3]);
            mma16816(s[2*p+1], ql[ks], th[2],  th[3]);
        }
    }

    float mx0 = -INFINITY, mx1 = -INFINITY;
    #pragma unroll
    for (int nj = 0; nj < 8; nj++) {
        if (DIAG) {
            int kc = kc_base + nj * 8 + (lane & 3) * 2;
            if (kc     > qrow0)     s[nj][0] = -INFINITY;
            if (kc + 1 > qrow0)     s[nj][1] = -INFINITY;
            if (kc     > qrow0 + 8) s[nj][2] = -INFINITY;
            if (kc + 1 > qrow0 + 8) s[nj][3] = -INFINITY;
        }
        mx0 = fmaxf(mx0, fmaxf(s[nj][0], s[nj][1]));
        mx1 = fmaxf(mx1, fmaxf(s[nj][2], s[nj][3]));
    }
    mx0 = fmaxf(mx0, __shfl_xor_sync(0xffffffffu, mx0, 1));
    mx0 = fmaxf(mx0, __shfl_xor_sync(0xffffffffu, mx0, 2));
    mx1 = fmaxf(mx1, __shfl_xor_sync(0xffffffffu, mx1, 1));
    mx1 = fmaxf(mx1, __shfl_xor_sync(0xffffffffu, mx1, 2));

    float nm0 = fmaxf(m0, mx0), nm1 = fmaxf(m1, mx1);
    float a0 = exp2f(m0 - nm0), a1 = exp2f(m1 - nm1);
    float rs0 = 0.f, rs1 = 0.f;
    #pragma unroll
    for (int nj = 0; nj < 8; nj++) {
        s[nj][0] = exp2f(s[nj][0] - nm0);
        s[nj][1] = exp2f(s[nj][1] - nm0);
        s[nj][2] = exp2f(s[nj][2] - nm1);
        s[nj][3] = exp2f(s[nj][3] - nm1);
        rs0 += s[nj][0] + s[nj][1];
        rs1 += s[nj][2] + s[nj][3];
    }
    rs0 += __shfl_xor_sync(0xffffffffu, rs0, 1);
    rs0 += __shfl_xor_sync(0xffffffffu, rs0, 2);
    rs1 += __shfl_xor_sync(0xffffffffu, rs1, 1);
    rs1 += __shfl_xor_sync(0xffffffffu, rs1, 2);
    l0 = l0 * a0 + rs0; l1 = l1 * a1 + rs1;
    m0 = nm0; m1 = nm1;
    #pragma unroll
    for (int dj = 0; dj < 8; dj++) {
        o[dj][0] *= a0; o[dj][1] *= a0;
        o[dj][2] *= a1; o[dj][3] *= a1;
    }

    #pragma unroll
    for (int kf = 0; kf < 4; kf++) {
        uint32_t ph[4], pl[4];
        split2(s[2*kf][0],   s[2*kf][1],   ph[0], pl[0]);
        split2(s[2*kf][2],   s[2*kf][3],   ph[1], pl[1]);
        split2(s[2*kf+1][0], s[2*kf+1][1], ph[2], pl[2]);
        split2(s[2*kf+1][2], s[2*kf+1][3], ph[3], pl[3]);
        #pragma unroll
        for (int dp = 0; dp < 4; dp++) {
            int row = kf * 16 + ((lane >> 3) & 1) * 8 + (lane & 7);
            int ch = dp * 2 + (lane >> 4);
            uint32_t sw = (uint32_t)((ch ^ (row & 7)) * 16);
            uint32_t vh4[4], vl4[4];
            ldmx4t(vh4, kb + 16384u + row * 128u + sw);
            ldmx4t(vl4, kb + 24576u + row * 128u + sw);
            mma16816(o[2*dp],   ph, vh4[0], vh4[1]);
            mma16816(o[2*dp],   ph, vl4[0], vl4[1]);
            mma16816(o[2*dp],   pl, vh4[0], vh4[1]);
            mma16816(o[2*dp+1], ph, vh4[2], vh4[3]);
            mma16816(o[2*dp+1], ph, vl4[2], vl4[3]);
            mma16816(o[2*dp+1], pl, vh4[2], vh4[3]);
        }
    }
}

// ---------------------------------------------------------------------------
// Tensor-core causal flash attention, split-bf16 (3-term) QK^T and PV.
// Q fragments loaded DIRECTLY from gmem; 3-stage KV ring (depth-2 prefetch);
// diagonal tile peeled. Grid: x = bh (32), y: qt = 31 - blockIdx.y.
// ---------------------------------------------------------------------------
#define ATTN_SMEM (3 * 32768 + 128)

__global__ __launch_bounds__(128, 2) void attn_mma_kernel(
    const __nv_bfloat16* __restrict__ Qh_g, const __nv_bfloat16* __restrict__ Ql_g,
    const __nv_bfloat16* __restrict__ Kh_g, const __nv_bfloat16* __restrict__ Kl_g,
    const __nv_bfloat16* __restrict__ Vh_g, const __nv_bfloat16* __restrict__ Vl_g,
    __nv_bfloat16* __restrict__ Oh, __nv_bfloat16* __restrict__ Ol)
{
    extern __shared__ char sraw[];
    uint32_t base = smem_u32(sraw);
    base = (base + 127) & ~127u;

    const int tid  = threadIdx.x;
    const int lane = tid & 31;
    const int wm   = tid >> 5;
    const int qt   = 31 - blockIdx.y;          // longest-first scheduling
    const int q0   = qt * 64;
    const int bh   = blockIdx.x;
    const size_t rowBase = (size_t)(bh >> 4) * L_SEQ;
    const int colBase = (bh & 15) * DHEAD;
    const int T = qt + 1;

    #define KVBASE(buf) (base + (uint32_t)(buf) * 32768u)

    #define ISSUE_KV(jt, buf) do { \
        const __nv_bfloat16* b0_ = Kh_g + (rowBase + (jt) * 64) * NFEAT + colBase; \
        const __nv_bfloat16* b1_ = Kl_g + (rowBase + (jt) * 64) * NFEAT + colBase; \
        const __nv_bfloat16* b2_ = Vh_g + (rowBase + (jt) * 64) * NFEAT + colBase; \
        const __nv_bfloat16* b3_ = Vl_g + (rowBase + (jt) * 64) * NFEAT + colBase; \
        _Pragma("unroll") \
        for (int s = 0; s < 16; s++) { \
            int i = tid + s * 128; \
            int tl = i >> 9, j = i & 511, row = j >> 3, ch = j & 7; \
            uint32_t dst = KVBASE(buf) + (uint32_t)tl * 8192u + row * 128u \
                         + ((ch ^ (row & 7)) * 16); \
            size_t off = (size_t)row * NFEAT + ch * 8; \
            const __nv_bfloat16* src = (tl == 0 ? b0_ : tl == 1 ? b1_ : \
                                        tl == 2 ? b2_ : b3_) + off; \
            CP_ASYNC16(dst, src); \
        } \
        CP_COMMIT(); \
    } while (0)

    // Q fragments straight from gmem (mma A-layout, 4B loads, pre-scaled)
    uint32_t qh[4][4], ql[4][4];
    {
        const size_t r0o = (rowBase + q0 + wm * 16 + (lane >> 2)) * NFEAT
                         + colBase + (lane & 3) * 2;
        #pragma unroll
        for (int ks = 0; ks < 4; ks++) {
            size_t k0 = r0o + ks * 16;
            qh[ks][0] = *(const uint32_t*)(Qh_g + k0);
            qh[ks][1] = *(const uint32_t*)(Qh_g + k0 + 8 * NFEAT);
            qh[ks][2] = *(const uint32_t*)(Qh_g + k0 + 8);
            qh[ks][3] = *(const uint32_t*)(Qh_g + k0 + 8 * NFEAT + 8);
            ql[ks][0] = *(const uint32_t*)(Ql_g + k0);
            ql[ks][1] = *(const uint32_t*)(Ql_g + k0 + 8 * NFEAT);
            ql[ks][2] = *(const uint32_t*)(Ql_g + k0 + 8);
            ql[ks][3] = *(const uint32_t*)(Ql_g + k0 + 8 * NFEAT + 8);
        }
    }

    ISSUE_KV(0, 0);
    if (T > 1) ISSUE_KV(1, 1);

    float m0 = -INFINITY, m1 = -INFINITY, l0 = 0.f, l1 = 0.f;
    float o[8][4];
    #pragma unroll
    for (int dj = 0; dj < 8; dj++)
        #pragma unroll
        for (int e = 0; e < 4; e++) o[dj][e] = 0.f;

    const int qrow0 = q0 + wm * 16 + (lane >> 2);

    // mainloop: t = 0 .. T-2 (no diagonal masking), 3-stage ring
    #pragma unroll 1
    for (int t = 0; t < T - 1; t++) {
        CP_WAIT(1);                            // stage t resident
        __syncthreads();                       // visible; (t+2)%3 readers done
        if (t + 2 < T) ISSUE_KV(t + 2, (t + 2) % 3);
        attn_step<false>(KVBASE(t % 3), lane, qrow0, t * 64,
                         qh, ql, m0, m1, l0, l1, o);
    }

    // final (diagonal) tile: t = T-1 = qt
    {
        const int t = T - 1;
        CP_WAIT(0);
        __syncthreads();
        attn_step<true>(KVBASE(t % 3), lane, qrow0, t * 64,
                        qh, ql, m0, m1, l0, l1, o);
    }

    const float i0 = 1.f / l0, i1 = 1.f / l1;
    const int qrow = q0 + wm * 16 + (lane >> 2);
    #pragma unroll
    for (int dj = 0; dj < 8; dj++) {
        int col = colBase + dj * 8 + (lane & 3) * 2;
        size_t off0 = (rowBase + qrow) * NFEAT + col;
        size_t off1 = (rowBase + qrow + 8) * NFEAT + col;
        uint32_t h, l;
        split2(o[dj][0] * i0, o[dj][1] * i0, h, l);
        *(uint32_t*)(Oh + off0) = h; *(uint32_t*)(Ol + off0) = l;
        split2(o[dj][2] * i1, o[dj][3] * i1, h, l);
        *(uint32_t*)(Oh + off1) = h; *(uint32_t*)(Ol + off1) = l;
    }
}

// ---------------------------------------------------------------------------
// Launch
// ---------------------------------------------------------------------------
extern "C" void kernel_launch(void* const* d_in, const int* in_sizes, int n_in,
                              void* d_out, int out_size)
{
    const float* X  = (const float*)d_in[0];
    const float* Wq = (const float*)d_in[1];
    const float* bq = (const float*)d_in[2];
    const float* Wk = (const float*)d_in[3];
    const float* bk = (const float*)d_in[4];
    const float* Wv = (const float*)d_in[5];
    const float* bv = (const float*)d_in[6];
    const float* Wo = (const float*)d_in[7];
    const float* bo = (const float*)d_in[8];
    float* out = (float*)d_out;

    __nv_bfloat16 *Ch, *Cl, *Xh, *Xl, *WallH, *WallL, *WpH, *WpL, *WoH, *WoL;
    __nv_bfloat16 *QKVH, *QKVL, *AH, *AL;
    float* bqkv;
    cudaGetSymbolAddress((void**)&Ch,    g_Ch);    cudaGetSymbolAddress((void**)&Cl,    g_Cl);
    cudaGetSymbolAddress((void**)&Xh,    g_Xh);    cudaGetSymbolAddress((void**)&Xl,    g_Xl);
    cudaGetSymbolAddress((void**)&WallH, g_WallH); cudaGetSymbolAddress((void**)&WallL, g_WallL);
    cudaGetSymbolAddress((void**)&WpH,   g_WpH);   cudaGetSymbolAddress((void**)&WpL,   g_WpL);
    cudaGetSymbolAddress((void**)&WoH,   g_WoH);   cudaGetSymbolAddress((void**)&WoL,   g_WoL);
    cudaGetSymbolAddress((void**)&QKVH,  g_QKVH);  cudaGetSymbolAddress((void**)&QKVL,  g_QKVL);
    cudaGetSymbolAddress((void**)&AH,    g_AH);    cudaGetSymbolAddress((void**)&AL,    g_AL);
    cudaGetSymbolAddress((void**)&bqkv,  g_bqkv);

    cudaFuncSetAttribute(mma_gemm_kernel,
                         cudaFuncAttributeMaxDynamicSharedMemorySize, GEMM_SMEM);
    cudaFuncSetAttribute(attn_mma_kernel,
                         cudaFuncAttributeMaxDynamicSharedMemorySize, ATTN_SMEM);

    // 1) unified prep (cos + splits + bias concat w/ QSCALE-scaled bq)
    prep_kernel<<<PREP_BLOCKS, 256>>>(X, Wq, Wk, Wv, Wo, bq, bk, bv);

    // 2) fold IFFT: W' = [Wq;Wk;Wv] @ C   (M=3072 -> grid (8,24))
    mma_gemm_kernel<<<dim3(8, 24), 256, GEMM_SMEM>>>(
        WallH, WallL, Ch, Cl, nullptr, nullptr, WpH, WpL, 0, 1.0f);

    // 3) fused QKV: [Q|K|V] = X @ W'^T (Q scaled by QSCALE) + bqkv
    mma_gemm_kernel<<<dim3(24, 32), 256, GEMM_SMEM>>>(
        Xh, Xl, WpH, WpL, bqkv, nullptr, QKVH, QKVL, (size_t)MTN, QSCALE);

    // 4) tensor-core causal attention (q-tile 64, longest blocks first)
    attn_mma_kernel<<<dim3(BATCH * NHEAD, L_SEQ / 64), 128, ATTN_SMEM>>>(
        QKVH, QKVL, QKVH + MTN, QKVL + MTN, QKVH + 2 * (size_t)MTN, QKVL + 2 * (size_t)MTN,
        AH, AL);

    // 5) out = A @ Wo^T + bo
    mma_gemm_kernel<<<dim3(8, 32), 256, GEMM_SMEM>>>(
        AH, AL, WoH, WoL, bo, out, nullptr, nullptr, 0, 1.0f);
}